// round 5
// baseline (speedup 1.0000x reference)
#include <cuda_runtime.h>
#include <cuda_bf16.h>
#include <cstdint>

// Problem constants
#define B_   2
#define N_   2048
#define D_   1024
#define H_   16
#define DH_  64
#define ROWS_ (B_ * N_)          // 4096 tokens
#define QKVW_ (3 * D_)           // 3072

// Scratch (static device memory; no allocation at runtime)
__device__ float g_qkv[(size_t)ROWS_ * QKVW_];   // 48 MB: q|k|v per token row
__device__ float g_ao [(size_t)ROWS_ * D_];      // 16 MB: attention output

// ---------------------------------------------------------------------------
// tf32 helpers
// ---------------------------------------------------------------------------
__device__ __forceinline__ uint32_t f32_to_tf32(float x) {
    uint32_t r;
    asm("cvt.rna.tf32.f32 %0, %1;" : "=r"(r) : "f"(x));
    return r;
}

__device__ __forceinline__ void mma_tf32_16x8x8(float* d,
                                                const uint32_t* a,
                                                const uint32_t* b) {
    asm volatile(
        "mma.sync.aligned.m16n8k8.row.col.f32.tf32.tf32.f32 "
        "{%0,%1,%2,%3}, {%4,%5,%6,%7}, {%8,%9}, {%0,%1,%2,%3};\n"
        : "+f"(d[0]), "+f"(d[1]), "+f"(d[2]), "+f"(d[3])
        : "r"(a[0]), "r"(a[1]), "r"(a[2]), "r"(a[3]),
          "r"(b[0]), "r"(b[1]));
}

// ---------------------------------------------------------------------------
// Kernel 1/4: tf32 tensor-core GEMM + bias.  C[M,N] = A[M,K] @ B[K,N] + bias
// Block 128x128, BK=16, 256 threads = 8 warps (4m x 2n), warp tile 32x64.
// Per warp: 2 m16-tiles x 8 n8-tiles of m16n8k8.
// A,B assumed row-major; M,N multiples of 128; K multiple of 16.
// ---------------------------------------------------------------------------
#define AS_STRIDE 20    // pad: conflict-free A-frag LDS (20g+t distinct banks)
#define BS_STRIDE 136   // pad: conflict-free B-frag LDS (8t+g distinct banks)

__global__ __launch_bounds__(256, 2)
void gemm_tf32_bias_kernel(const float* __restrict__ A, const float* __restrict__ B,
                           const float* __restrict__ bias, float* __restrict__ C,
                           int M, int N, int K)
{
    __shared__ uint32_t As[128 * AS_STRIDE];   // [m][k] k=0..15
    __shared__ uint32_t Bs[16 * BS_STRIDE];    // [k][n] n=0..127

    const int tid  = threadIdx.x;
    const int lane = tid & 31;
    const int w    = tid >> 5;          // 0..7
    const int wm   = w & 3;             // 0..3  (m)
    const int wn   = w >> 2;            // 0..1  (n)
    const int g    = lane >> 2;         // groupID 0..7
    const int t    = lane & 3;          // threadID-in-group 0..3

    const int row0 = blockIdx.y * 128;
    const int col0 = blockIdx.x * 128;

    // Gmem load indices
    const int ar = tid >> 2;            // 0..63
    const int ac = (tid & 3) * 4;       // 0,4,8,12
    const int br = tid >> 5;            // 0..7
    const int bc = (tid & 31) * 4;      // 0..124

    const float* Ap0 = A + (size_t)(row0 + ar) * K + ac;
    const float* Ap1 = A + (size_t)(row0 + ar + 64) * K + ac;
    const float* Bp0 = B + (size_t)br * N + col0 + bc;
    const float* Bp1 = B + (size_t)(br + 8) * N + col0 + bc;

    float acc[2][8][4];
#pragma unroll
    for (int mt = 0; mt < 2; mt++)
#pragma unroll
        for (int nt = 0; nt < 8; nt++)
#pragma unroll
            for (int i = 0; i < 4; i++) acc[mt][nt][i] = 0.f;

    for (int k0 = 0; k0 < K; k0 += 16) {
        // Load + convert A tile (128x16) and B tile (16x128)
        float4 a0 = *(const float4*)(Ap0 + k0);
        float4 a1 = *(const float4*)(Ap1 + k0);
        float4 b0 = *(const float4*)(Bp0 + (size_t)k0 * N);
        float4 b1 = *(const float4*)(Bp1 + (size_t)k0 * N);
        __syncthreads();   // protect smem from previous iteration's readers
        uint32_t* asr0 = &As[ar * AS_STRIDE + ac];
        asr0[0] = f32_to_tf32(a0.x); asr0[1] = f32_to_tf32(a0.y);
        asr0[2] = f32_to_tf32(a0.z); asr0[3] = f32_to_tf32(a0.w);
        uint32_t* asr1 = &As[(ar + 64) * AS_STRIDE + ac];
        asr1[0] = f32_to_tf32(a1.x); asr1[1] = f32_to_tf32(a1.y);
        asr1[2] = f32_to_tf32(a1.z); asr1[3] = f32_to_tf32(a1.w);
        uint32_t* bsr0 = &Bs[br * BS_STRIDE + bc];
        bsr0[0] = f32_to_tf32(b0.x); bsr0[1] = f32_to_tf32(b0.y);
        bsr0[2] = f32_to_tf32(b0.z); bsr0[3] = f32_to_tf32(b0.w);
        uint32_t* bsr1 = &Bs[(br + 8) * BS_STRIDE + bc];
        bsr1[0] = f32_to_tf32(b1.x); bsr1[1] = f32_to_tf32(b1.y);
        bsr1[2] = f32_to_tf32(b1.z); bsr1[3] = f32_to_tf32(b1.w);
        __syncthreads();

#pragma unroll
        for (int ks = 0; ks < 16; ks += 8) {
            // A fragments: 2 m16 tiles
            uint32_t afr[2][4];
#pragma unroll
            for (int mt = 0; mt < 2; mt++) {
                int r = wm * 32 + mt * 16 + g;
                afr[mt][0] = As[r * AS_STRIDE + ks + t];
                afr[mt][1] = As[(r + 8) * AS_STRIDE + ks + t];
                afr[mt][2] = As[r * AS_STRIDE + ks + t + 4];
                afr[mt][3] = As[(r + 8) * AS_STRIDE + ks + t + 4];
            }
            // B fragments: 8 n8 tiles
            uint32_t bfr[8][2];
#pragma unroll
            for (int nt = 0; nt < 8; nt++) {
                int n = wn * 64 + nt * 8 + g;
                bfr[nt][0] = Bs[(ks + t) * BS_STRIDE + n];
                bfr[nt][1] = Bs[(ks + t + 4) * BS_STRIDE + n];
            }
#pragma unroll
            for (int mt = 0; mt < 2; mt++)
#pragma unroll
                for (int nt = 0; nt < 8; nt++)
                    mma_tf32_16x8x8(acc[mt][nt], afr[mt], bfr[nt]);
        }
    }

    // Epilogue: bias + store.
    // C frag layout: c0:(g, 2t) c1:(g, 2t+1) c2:(g+8, 2t) c3:(g+8, 2t+1)
#pragma unroll
    for (int mt = 0; mt < 2; mt++) {
        int r0 = row0 + wm * 32 + mt * 16 + g;
#pragma unroll
        for (int nt = 0; nt < 8; nt++) {
            int c = col0 + wn * 64 + nt * 8 + 2 * t;
            float bv0 = bias[c], bv1 = bias[c + 1];
            float2 v0 = make_float2(acc[mt][nt][0] + bv0, acc[mt][nt][1] + bv1);
            float2 v1 = make_float2(acc[mt][nt][2] + bv0, acc[mt][nt][3] + bv1);
            *(float2*)(C + (size_t)r0 * N + c)       = v0;
            *(float2*)(C + (size_t)(r0 + 8) * N + c) = v1;
        }
    }
}

// ---------------------------------------------------------------------------
// Kernel 2/4: RMSNorm(q), RMSNorm(k) + RoPE(q), RoPE(k) in-place on g_qkv.
// ---------------------------------------------------------------------------
__global__ __launch_bounds__(256)
void norm_rope_kernel(float* __restrict__ qkv,
                      const float* __restrict__ cosb, const float* __restrict__ sinb,
                      const float* __restrict__ q_scale, const float* __restrict__ k_scale)
{
    int row = blockIdx.x;
    int n = row & (N_ - 1);
    float* q = qkv + (size_t)row * QKVW_;
    float* k = q + D_;
    int tid = threadIdx.x;

    float sq = 0.f, sk = 0.f;
    for (int i = tid; i < D_; i += 256) {
        float a = q[i]; sq += a * a;
        float b = k[i]; sk += b * b;
    }
#pragma unroll
    for (int o = 16; o; o >>= 1) {
        sq += __shfl_xor_sync(0xffffffffu, sq, o);
        sk += __shfl_xor_sync(0xffffffffu, sk, o);
    }
    __shared__ float rq_s[8], rk_s[8];
    int w = tid >> 5, lane = tid & 31;
    if (lane == 0) { rq_s[w] = sq; rk_s[w] = sk; }
    __syncthreads();
    if (tid == 0) {
        float a = 0.f, b = 0.f;
#pragma unroll
        for (int i = 0; i < 8; i++) { a += rq_s[i]; b += rk_s[i]; }
        rq_s[0] = rsqrtf(a * (1.f / D_) + 1e-6f);
        rk_s[0] = rsqrtf(b * (1.f / D_) + 1e-6f);
    }
    __syncthreads();
    float rq = rq_s[0], rk = rk_s[0];

    for (int p = tid; p < 512; p += 256) {
        int hh = p >> 5, m = p & 31;
        int i0 = hh * 64 + 2 * m;
        float c = cosb[n * 32 + m];
        float s = sinb[n * 32 + m];
        float q0 = q[i0] * rq * q_scale[i0];
        float q1 = q[i0 + 1] * rq * q_scale[i0 + 1];
        q[i0]     = q0 * c - q1 * s;
        q[i0 + 1] = q0 * s + q1 * c;
        float k0 = k[i0] * rk * k_scale[i0];
        float k1 = k[i0 + 1] * rk * k_scale[i0 + 1];
        k[i0]     = k0 * c - k1 * s;
        k[i0 + 1] = k0 * s + k1 * c;
    }
}

// ---------------------------------------------------------------------------
// Kernel 3/4: flash-style attention, fp32 (unchanged from baseline design).
// ---------------------------------------------------------------------------
#define ATTN_SMEM_BYTES (16832 * 4)

__global__ __launch_bounds__(256, 3)
void attn_kernel(const float* __restrict__ qkv, float* __restrict__ out)
{
    extern __shared__ float sm[];
    float* Qs   = sm;
    float* Ks   = Qs + 4096;
    float* Vs   = Ks + 4096;
    float* Ps   = Vs + 4096;            // stride 68
    float* m_s  = Ps + 64 * 68;
    float* l_s  = m_s + 64;
    float* al_s = l_s + 64;

    int tid = threadIdx.x;
    int tx = tid & 15, ty = tid >> 4;
    int qt = blockIdx.x, h = blockIdx.y, b = blockIdx.z;

    const float* qg = qkv + ((size_t)(b * N_ + qt * 64) * QKVW_) + h * DH_;

    {
        int r = tid >> 2, seg = tid & 3;
        const float4* src = (const float4*)(qg + (size_t)r * QKVW_ + seg * 16);
#pragma unroll
        for (int i = 0; i < 4; i++) {
            float4 v = src[i];
            int dd = seg * 16 + i * 4;
            Qs[(dd + 0) * 64 + r] = v.x;
            Qs[(dd + 1) * 64 + r] = v.y;
            Qs[(dd + 2) * 64 + r] = v.z;
            Qs[(dd + 3) * 64 + r] = v.w;
        }
    }
    if (tid < 64) { m_s[tid] = -1e30f; l_s[tid] = 0.f; }

    float acc[4][4];
#pragma unroll
    for (int i = 0; i < 4; i++)
#pragma unroll
        for (int j = 0; j < 4; j++) acc[i][j] = 0.f;

    const float scale = 0.125f;

    for (int kt = 0; kt < N_ / 64; kt++) {
        __syncthreads();
        {
            int c = tid >> 2, seg = tid & 3;
            const float* kg = qkv + ((size_t)(b * N_ + kt * 64) * QKVW_) + D_ + h * DH_;
            const float4* ksrc = (const float4*)(kg + (size_t)c * QKVW_ + seg * 16);
#pragma unroll
            for (int i = 0; i < 4; i++) {
                float4 v = ksrc[i];
                int dd = seg * 16 + i * 4;
                Ks[(dd + 0) * 64 + c] = v.x;
                Ks[(dd + 1) * 64 + c] = v.y;
                Ks[(dd + 2) * 64 + c] = v.z;
                Ks[(dd + 3) * 64 + c] = v.w;
            }
            const float4* vsrc = (const float4*)(kg + D_ + (size_t)c * QKVW_ + seg * 16);
            float4* vdst = (float4*)(Vs + c * 64 + seg * 16);
#pragma unroll
            for (int i = 0; i < 4; i++) vdst[i] = vsrc[i];
        }
        __syncthreads();

        float s[4][4];
#pragma unroll
        for (int i = 0; i < 4; i++)
#pragma unroll
            for (int j = 0; j < 4; j++) s[i][j] = 0.f;

#pragma unroll 8
        for (int dd = 0; dd < DH_; dd++) {
            float4 a  = *(const float4*)(Qs + dd * 64 + ty * 4);
            float4 bb = *(const float4*)(Ks + dd * 64 + tx * 4);
            float av[4] = {a.x, a.y, a.z, a.w};
            float bw[4] = {bb.x, bb.y, bb.z, bb.w};
#pragma unroll
            for (int i = 0; i < 4; i++)
#pragma unroll
                for (int j = 0; j < 4; j++)
                    s[i][j] = fmaf(av[i], bw[j], s[i][j]);
        }
#pragma unroll
        for (int j = 0; j < 4; j++)
#pragma unroll
            for (int i = 0; i < 4; i++)
                Ps[(tx * 4 + j) * 68 + ty * 4 + i] = s[i][j] * scale;
        __syncthreads();

        {
            int row = tid >> 2, sub = tid & 3;
            float mx = -1e30f;
#pragma unroll
            for (int k2 = sub * 16; k2 < sub * 16 + 16; k2++)
                mx = fmaxf(mx, Ps[k2 * 68 + row]);
            mx = fmaxf(mx, __shfl_xor_sync(0xffffffffu, mx, 1));
            mx = fmaxf(mx, __shfl_xor_sync(0xffffffffu, mx, 2));
            float mnew = fmaxf(m_s[row], mx);
            float sum = 0.f;
#pragma unroll
            for (int k2 = sub * 16; k2 < sub * 16 + 16; k2++) {
                float e = __expf(Ps[k2 * 68 + row] - mnew);
                Ps[k2 * 68 + row] = e;
                sum += e;
            }
            sum += __shfl_xor_sync(0xffffffffu, sum, 1);
            sum += __shfl_xor_sync(0xffffffffu, sum, 2);
            if (sub == 0) {
                float alpha = __expf(m_s[row] - mnew);
                al_s[row] = alpha;
                l_s[row]  = l_s[row] * alpha + sum;
                m_s[row]  = mnew;
            }
        }
        __syncthreads();

        float alr[4];
#pragma unroll
        for (int i = 0; i < 4; i++) alr[i] = al_s[ty * 4 + i];
#pragma unroll
        for (int i = 0; i < 4; i++)
#pragma unroll
            for (int j = 0; j < 4; j++) acc[i][j] *= alr[i];

#pragma unroll 8
        for (int k2 = 0; k2 < 64; k2++) {
            float4 p  = *(const float4*)(Ps + k2 * 68 + ty * 4);
            float4 vv = *(const float4*)(Vs + k2 * 64 + tx * 4);
            float pv[4] = {p.x, p.y, p.z, p.w};
            float vw[4] = {vv.x, vv.y, vv.z, vv.w};
#pragma unroll
            for (int i = 0; i < 4; i++)
#pragma unroll
                for (int j = 0; j < 4; j++)
                    acc[i][j] = fmaf(pv[i], vw[j], acc[i][j]);
        }
    }

    float* og = out + ((size_t)(b * N_ + qt * 64) * D_) + h * DH_;
#pragma unroll
    for (int i = 0; i < 4; i++) {
        float inv = 1.f / l_s[ty * 4 + i];
        float4 o;
        o.x = acc[i][0] * inv;
        o.y = acc[i][1] * inv;
        o.z = acc[i][2] * inv;
        o.w = acc[i][3] * inv;
        *(float4*)(og + (size_t)(ty * 4 + i) * D_ + tx * 4) = o;
    }
}

// ---------------------------------------------------------------------------
extern "C" void kernel_launch(void* const* d_in, const int* in_sizes, int n_in,
                              void* d_out, int out_size)
{
    const float* x       = (const float*)d_in[0];   // [2,2048,1024]
    const float* cosb    = (const float*)d_in[1];   // [2048,32]
    const float* sinb    = (const float*)d_in[2];   // [2048,32]
    const float* Wqkv    = (const float*)d_in[3];   // [1024,3072]
    const float* bqkv    = (const float*)d_in[4];   // [3072]
    const float* q_scale = (const float*)d_in[5];   // [1024]
    const float* k_scale = (const float*)d_in[6];   // [1024]
    const float* Wout    = (const float*)d_in[7];   // [1024,1024]
    const float* bout    = (const float*)d_in[8];   // [1024]
    float* out = (float*)d_out;                     // [2,2048,1024]

    float* qkv_p = nullptr;
    float* ao_p  = nullptr;
    cudaGetSymbolAddress((void**)&qkv_p, g_qkv);
    cudaGetSymbolAddress((void**)&ao_p, g_ao);
    cudaFuncSetAttribute(attn_kernel, cudaFuncAttributeMaxDynamicSharedMemorySize,
                         ATTN_SMEM_BYTES);

    // 1) qkv = x @ Wqkv + bqkv   (tf32 tensor cores)
    {
        dim3 grid(QKVW_ / 128, ROWS_ / 128);
        gemm_tf32_bias_kernel<<<grid, 256>>>(x, Wqkv, bqkv, qkv_p, ROWS_, QKVW_, D_);
    }
    // 2) rmsnorm + rope on q,k (in place)
    norm_rope_kernel<<<ROWS_, 256>>>(qkv_p, cosb, sinb, q_scale, k_scale);

    // 3) attention (fp32)
    {
        dim3 grid(N_ / 64, H_, B_);
        attn_kernel<<<grid, 256, ATTN_SMEM_BYTES>>>(qkv_p, ao_p);
    }
    // 4) out = ao @ Wout + bout   (tf32 tensor cores)
    {
        dim3 grid(D_ / 128, ROWS_ / 128);
        gemm_tf32_bias_kernel<<<grid, 256>>>(ao_p, Wout, bout, out, ROWS_, D_, D_);
    }
}

// round 12
// speedup vs baseline: 1.7539x; 1.7539x over previous
#include <cuda_runtime.h>
#include <cuda_bf16.h>
#include <cstdint>

// Problem constants
#define B_   2
#define N_   2048
#define D_   1024
#define H_   16
#define DH_  64
#define ROWS_ (B_ * N_)          // 4096 tokens
#define QKVW_ (3 * D_)           // 3072

// Scratch (static device memory; no allocation at runtime)
__device__ float g_qkv[(size_t)ROWS_ * QKVW_];   // 48 MB: q|k|v per token row
__device__ float g_ao [(size_t)ROWS_ * D_];      // 16 MB: attention output

// ---------------------------------------------------------------------------
// tf32 helpers
// ---------------------------------------------------------------------------
__device__ __forceinline__ uint32_t f32_to_tf32(float x) {
    uint32_t r;
    asm("cvt.rna.tf32.f32 %0, %1;" : "=r"(r) : "f"(x));
    return r;
}

__device__ __forceinline__ void mma_tf32_16x8x8(float* d,
                                                const uint32_t* a,
                                                const uint32_t* b) {
    asm volatile(
        "mma.sync.aligned.m16n8k8.row.col.f32.tf32.tf32.f32 "
        "{%0,%1,%2,%3}, {%4,%5,%6,%7}, {%8,%9}, {%0,%1,%2,%3};\n"
        : "+f"(d[0]), "+f"(d[1]), "+f"(d[2]), "+f"(d[3])
        : "r"(a[0]), "r"(a[1]), "r"(a[2]), "r"(a[3]),
          "r"(b[0]), "r"(b[1]));
}

// ---------------------------------------------------------------------------
// Kernel 1/4: tf32 tensor-core GEMM + bias (validated in R5).
// ---------------------------------------------------------------------------
#define AS_STRIDE 20
#define BS_STRIDE 136

__global__ __launch_bounds__(256, 2)
void gemm_tf32_bias_kernel(const float* __restrict__ A, const float* __restrict__ B,
                           const float* __restrict__ bias, float* __restrict__ C,
                           int M, int N, int K)
{
    __shared__ uint32_t As[128 * AS_STRIDE];
    __shared__ uint32_t Bs[16 * BS_STRIDE];

    const int tid  = threadIdx.x;
    const int lane = tid & 31;
    const int w    = tid >> 5;
    const int wm   = w & 3;
    const int wn   = w >> 2;
    const int g    = lane >> 2;
    const int t    = lane & 3;

    const int row0 = blockIdx.y * 128;
    const int col0 = blockIdx.x * 128;

    const int ar = tid >> 2;
    const int ac = (tid & 3) * 4;
    const int br = tid >> 5;
    const int bc = (tid & 31) * 4;

    const float* Ap0 = A + (size_t)(row0 + ar) * K + ac;
    const float* Ap1 = A + (size_t)(row0 + ar + 64) * K + ac;
    const float* Bp0 = B + (size_t)br * N + col0 + bc;
    const float* Bp1 = B + (size_t)(br + 8) * N + col0 + bc;

    float acc[2][8][4];
#pragma unroll
    for (int mt = 0; mt < 2; mt++)
#pragma unroll
        for (int nt = 0; nt < 8; nt++)
#pragma unroll
            for (int i = 0; i < 4; i++) acc[mt][nt][i] = 0.f;

    for (int k0 = 0; k0 < K; k0 += 16) {
        float4 a0 = *(const float4*)(Ap0 + k0);
        float4 a1 = *(const float4*)(Ap1 + k0);
        float4 b0 = *(const float4*)(Bp0 + (size_t)k0 * N);
        float4 b1 = *(const float4*)(Bp1 + (size_t)k0 * N);
        __syncthreads();
        uint32_t* asr0 = &As[ar * AS_STRIDE + ac];
        asr0[0] = f32_to_tf32(a0.x); asr0[1] = f32_to_tf32(a0.y);
        asr0[2] = f32_to_tf32(a0.z); asr0[3] = f32_to_tf32(a0.w);
        uint32_t* asr1 = &As[(ar + 64) * AS_STRIDE + ac];
        asr1[0] = f32_to_tf32(a1.x); asr1[1] = f32_to_tf32(a1.y);
        asr1[2] = f32_to_tf32(a1.z); asr1[3] = f32_to_tf32(a1.w);
        uint32_t* bsr0 = &Bs[br * BS_STRIDE + bc];
        bsr0[0] = f32_to_tf32(b0.x); bsr0[1] = f32_to_tf32(b0.y);
        bsr0[2] = f32_to_tf32(b0.z); bsr0[3] = f32_to_tf32(b0.w);
        uint32_t* bsr1 = &Bs[(br + 8) * BS_STRIDE + bc];
        bsr1[0] = f32_to_tf32(b1.x); bsr1[1] = f32_to_tf32(b1.y);
        bsr1[2] = f32_to_tf32(b1.z); bsr1[3] = f32_to_tf32(b1.w);
        __syncthreads();

#pragma unroll
        for (int ks = 0; ks < 16; ks += 8) {
            uint32_t afr[2][4];
#pragma unroll
            for (int mt = 0; mt < 2; mt++) {
                int r = wm * 32 + mt * 16 + g;
                afr[mt][0] = As[r * AS_STRIDE + ks + t];
                afr[mt][1] = As[(r + 8) * AS_STRIDE + ks + t];
                afr[mt][2] = As[r * AS_STRIDE + ks + t + 4];
                afr[mt][3] = As[(r + 8) * AS_STRIDE + ks + t + 4];
            }
            uint32_t bfr[8][2];
#pragma unroll
            for (int nt = 0; nt < 8; nt++) {
                int n = wn * 64 + nt * 8 + g;
                bfr[nt][0] = Bs[(ks + t) * BS_STRIDE + n];
                bfr[nt][1] = Bs[(ks + t + 4) * BS_STRIDE + n];
            }
#pragma unroll
            for (int mt = 0; mt < 2; mt++)
#pragma unroll
                for (int nt = 0; nt < 8; nt++)
                    mma_tf32_16x8x8(acc[mt][nt], afr[mt], bfr[nt]);
        }
    }

#pragma unroll
    for (int mt = 0; mt < 2; mt++) {
        int r0 = row0 + wm * 32 + mt * 16 + g;
#pragma unroll
        for (int nt = 0; nt < 8; nt++) {
            int c = col0 + wn * 64 + nt * 8 + 2 * t;
            float bv0 = bias[c], bv1 = bias[c + 1];
            float2 v0 = make_float2(acc[mt][nt][0] + bv0, acc[mt][nt][1] + bv1);
            float2 v1 = make_float2(acc[mt][nt][2] + bv0, acc[mt][nt][3] + bv1);
            *(float2*)(C + (size_t)r0 * N + c)       = v0;
            *(float2*)(C + (size_t)(r0 + 8) * N + c) = v1;
        }
    }
}

// ---------------------------------------------------------------------------
// Kernel 2/4: RMSNorm + RoPE (unchanged, validated).
// ---------------------------------------------------------------------------
__global__ __launch_bounds__(256)
void norm_rope_kernel(float* __restrict__ qkv,
                      const float* __restrict__ cosb, const float* __restrict__ sinb,
                      const float* __restrict__ q_scale, const float* __restrict__ k_scale)
{
    int row = blockIdx.x;
    int n = row & (N_ - 1);
    float* q = qkv + (size_t)row * QKVW_;
    float* k = q + D_;
    int tid = threadIdx.x;

    float sq = 0.f, sk = 0.f;
    for (int i = tid; i < D_; i += 256) {
        float a = q[i]; sq += a * a;
        float b = k[i]; sk += b * b;
    }
#pragma unroll
    for (int o = 16; o; o >>= 1) {
        sq += __shfl_xor_sync(0xffffffffu, sq, o);
        sk += __shfl_xor_sync(0xffffffffu, sk, o);
    }
    __shared__ float rq_s[8], rk_s[8];
    int w = tid >> 5, lane = tid & 31;
    if (lane == 0) { rq_s[w] = sq; rk_s[w] = sk; }
    __syncthreads();
    if (tid == 0) {
        float a = 0.f, b = 0.f;
#pragma unroll
        for (int i = 0; i < 8; i++) { a += rq_s[i]; b += rk_s[i]; }
        rq_s[0] = rsqrtf(a * (1.f / D_) + 1e-6f);
        rk_s[0] = rsqrtf(b * (1.f / D_) + 1e-6f);
    }
    __syncthreads();
    float rq = rq_s[0], rk = rk_s[0];

    for (int p = tid; p < 512; p += 256) {
        int hh = p >> 5, m = p & 31;
        int i0 = hh * 64 + 2 * m;
        float c = cosb[n * 32 + m];
        float s = sinb[n * 32 + m];
        float q0 = q[i0] * rq * q_scale[i0];
        float q1 = q[i0 + 1] * rq * q_scale[i0 + 1];
        q[i0]     = q0 * c - q1 * s;
        q[i0 + 1] = q0 * s + q1 * c;
        float k0 = k[i0] * rk * k_scale[i0];
        float k1 = k[i0 + 1] * rk * k_scale[i0 + 1];
        k[i0]     = k0 * c - k1 * s;
        k[i0 + 1] = k0 * s + k1 * c;
    }
}

// ---------------------------------------------------------------------------
// Kernel 3/4: tensor-core flash attention (tf32 mma, FA2 online softmax).
// Block = (64 q-rows, head, batch). 128 threads = 4 warps x 16 rows.
// kv chunks of 64. All mma are m16n8k8 tf32.
// Smem: Ks[64][68] tf32, Vs[64][72] tf32, Pw[4][16][68] tf32.
//   Ks stride 68 -> QK B-frag (4g+t) conflict-free, Q A-frag staging too.
//   Vs stride 72 -> PV B-frag (8t+g) conflict-free.
//   Pw stride 68 -> PV A-frag (4g+t) conflict-free, warp-private.
// ---------------------------------------------------------------------------
#define KS_STRIDE 68
#define VS_STRIDE 72
#define PW_STRIDE 68
#define ATTN_TC_SMEM ((64 * KS_STRIDE + 64 * VS_STRIDE + 4 * 16 * PW_STRIDE) * 4)

__global__ __launch_bounds__(128, 3)
void attn_tc_kernel(const float* __restrict__ qkv, float* __restrict__ out)
{
    extern __shared__ uint32_t smu[];
    uint32_t* Ks = smu;                        // [64][KS_STRIDE]
    uint32_t* Vs = Ks + 64 * KS_STRIDE;        // [64][VS_STRIDE]
    uint32_t* Pw = Vs + 64 * VS_STRIDE;        // [4][16][PW_STRIDE]

    const int tid  = threadIdx.x;
    const int lane = tid & 31;
    const int w    = tid >> 5;     // warp 0..3 -> rows w*16..w*16+15
    const int g    = lane >> 2;    // 0..7
    const int t    = lane & 3;     // 0..3

    const int q0 = blockIdx.x * 64;
    const int h  = blockIdx.y;
    const int b  = blockIdx.z;

    const float* qg = qkv + (size_t)(b * N_ + q0) * QKVW_ + h * DH_;
    const float* kg = qkv + (size_t)(b * N_) * QKVW_ + D_ + h * DH_;
    const float* vg = kg + D_;

    // ---- Stage Q (pre-scaled by d^-0.5 = 0.125, exact) into Ks, grab A-frags
    {
        int r = tid >> 1, c = (tid & 1) * 32;
        const float* src = qg + (size_t)r * QKVW_ + c;
        uint32_t* dst = Ks + r * KS_STRIDE + c;
#pragma unroll
        for (int i = 0; i < 32; i += 4) {
            float4 v = *(const float4*)(src + i);
            dst[i + 0] = f32_to_tf32(v.x * 0.125f);
            dst[i + 1] = f32_to_tf32(v.y * 0.125f);
            dst[i + 2] = f32_to_tf32(v.z * 0.125f);
            dst[i + 3] = f32_to_tf32(v.w * 0.125f);
        }
    }
    __syncthreads();
    uint32_t qf[8][4];
    {
        int r = w * 16 + g;
#pragma unroll
        for (int kk = 0; kk < 8; kk++) {
            qf[kk][0] = Ks[r * KS_STRIDE + kk * 8 + t];
            qf[kk][1] = Ks[(r + 8) * KS_STRIDE + kk * 8 + t];
            qf[kk][2] = Ks[r * KS_STRIDE + kk * 8 + t + 4];
            qf[kk][3] = Ks[(r + 8) * KS_STRIDE + kk * 8 + t + 4];
        }
    }

    float oacc[8][4];
#pragma unroll
    for (int nt = 0; nt < 8; nt++)
#pragma unroll
        for (int i = 0; i < 4; i++) oacc[nt][i] = 0.f;
    float m0 = -1e30f, m1 = -1e30f, l0 = 0.f, l1 = 0.f;

    uint32_t* pwme = Pw + w * 16 * PW_STRIDE;

    for (int kc = 0; kc < N_ / 64; kc++) {
        __syncthreads();   // previous iter's consumers done before overwrite
        // ---- Load K and V chunk (64 rows x 64), cvt to tf32
        {
            int r = tid >> 1, c = (tid & 1) * 32;
            const float* ksrc = kg + (size_t)(kc * 64 + r) * QKVW_ + c;
            const float* vsrc = vg + (size_t)(kc * 64 + r) * QKVW_ + c;
            uint32_t* kd = Ks + r * KS_STRIDE + c;
            uint32_t* vd = Vs + r * VS_STRIDE + c;
#pragma unroll
            for (int i = 0; i < 32; i += 4) {
                float4 kv = *(const float4*)(ksrc + i);
                kd[i + 0] = f32_to_tf32(kv.x);
                kd[i + 1] = f32_to_tf32(kv.y);
                kd[i + 2] = f32_to_tf32(kv.z);
                kd[i + 3] = f32_to_tf32(kv.w);
                float4 vv = *(const float4*)(vsrc + i);
                vd[i + 0] = f32_to_tf32(vv.x);
                vd[i + 1] = f32_to_tf32(vv.y);
                vd[i + 2] = f32_to_tf32(vv.z);
                vd[i + 3] = f32_to_tf32(vv.w);
            }
        }
        __syncthreads();

        // ---- S = Q K^T (scaled): 8 n-tiles x 8 k-steps
        float s[8][4];
#pragma unroll
        for (int nt = 0; nt < 8; nt++) {
            s[nt][0] = 0.f; s[nt][1] = 0.f; s[nt][2] = 0.f; s[nt][3] = 0.f;
        }
#pragma unroll
        for (int kk = 0; kk < 8; kk++) {
#pragma unroll
            for (int nt = 0; nt < 8; nt++) {
                uint32_t bf[2];
                bf[0] = Ks[(nt * 8 + g) * KS_STRIDE + kk * 8 + t];
                bf[1] = Ks[(nt * 8 + g) * KS_STRIDE + kk * 8 + t + 4];
                mma_tf32_16x8x8(s[nt], qf[kk], bf);
            }
        }

        // ---- Online softmax in fragment registers (rows g and g+8)
        float tm0 = -1e30f, tm1 = -1e30f;
#pragma unroll
        for (int nt = 0; nt < 8; nt++) {
            tm0 = fmaxf(tm0, fmaxf(s[nt][0], s[nt][1]));
            tm1 = fmaxf(tm1, fmaxf(s[nt][2], s[nt][3]));
        }
        tm0 = fmaxf(tm0, __shfl_xor_sync(0xffffffffu, tm0, 1));
        tm0 = fmaxf(tm0, __shfl_xor_sync(0xffffffffu, tm0, 2));
        tm1 = fmaxf(tm1, __shfl_xor_sync(0xffffffffu, tm1, 1));
        tm1 = fmaxf(tm1, __shfl_xor_sync(0xffffffffu, tm1, 2));
        float mn0 = fmaxf(m0, tm0), mn1 = fmaxf(m1, tm1);
        float al0 = __expf(m0 - mn0), al1 = __expf(m1 - mn1);
        m0 = mn0; m1 = mn1;

        float sum0 = 0.f, sum1 = 0.f;
#pragma unroll
        for (int nt = 0; nt < 8; nt++) {
            s[nt][0] = __expf(s[nt][0] - mn0);
            s[nt][1] = __expf(s[nt][1] - mn0);
            s[nt][2] = __expf(s[nt][2] - mn1);
            s[nt][3] = __expf(s[nt][3] - mn1);
            sum0 += s[nt][0] + s[nt][1];
            sum1 += s[nt][2] + s[nt][3];
        }
        sum0 += __shfl_xor_sync(0xffffffffu, sum0, 1);
        sum0 += __shfl_xor_sync(0xffffffffu, sum0, 2);
        sum1 += __shfl_xor_sync(0xffffffffu, sum1, 1);
        sum1 += __shfl_xor_sync(0xffffffffu, sum1, 2);
        l0 = l0 * al0 + sum0;
        l1 = l1 * al1 + sum1;

        // ---- Rescale O accumulator
#pragma unroll
        for (int nt = 0; nt < 8; nt++) {
            oacc[nt][0] *= al0; oacc[nt][1] *= al0;
            oacc[nt][2] *= al1; oacc[nt][3] *= al1;
        }

        // ---- Write P (tf32) to warp-private smem for A-frag re-layout
#pragma unroll
        for (int nt = 0; nt < 8; nt++) {
            uint2 v0, v1;
            v0.x = f32_to_tf32(s[nt][0]); v0.y = f32_to_tf32(s[nt][1]);
            v1.x = f32_to_tf32(s[nt][2]); v1.y = f32_to_tf32(s[nt][3]);
            *(uint2*)&pwme[g * PW_STRIDE + nt * 8 + 2 * t]       = v0;
            *(uint2*)&pwme[(g + 8) * PW_STRIDE + nt * 8 + 2 * t] = v1;
        }
        __syncwarp();

        // ---- O += P @ V : 8 k-steps (kv) x 8 n-tiles (d)
#pragma unroll
        for (int kk = 0; kk < 8; kk++) {
            uint32_t af[4];
            af[0] = pwme[g * PW_STRIDE + kk * 8 + t];
            af[1] = pwme[(g + 8) * PW_STRIDE + kk * 8 + t];
            af[2] = pwme[g * PW_STRIDE + kk * 8 + t + 4];
            af[3] = pwme[(g + 8) * PW_STRIDE + kk * 8 + t + 4];
#pragma unroll
            for (int nt = 0; nt < 8; nt++) {
                uint32_t bf[2];
                bf[0] = Vs[(kk * 8 + t) * VS_STRIDE + nt * 8 + g];
                bf[1] = Vs[(kk * 8 + t + 4) * VS_STRIDE + nt * 8 + g];
                mma_tf32_16x8x8(oacc[nt], af, bf);
            }
        }
        __syncwarp();   // Pw stable before next iteration's overwrite
    }

    // ---- Finalize: divide by l, store
    float inv0 = 1.f / l0, inv1 = 1.f / l1;
    float* og = out + (size_t)(b * N_ + q0 + w * 16) * D_ + h * DH_;
#pragma unroll
    for (int nt = 0; nt < 8; nt++) {
        float2 r0 = make_float2(oacc[nt][0] * inv0, oacc[nt][1] * inv0);
        float2 r1 = make_float2(oacc[nt][2] * inv1, oacc[nt][3] * inv1);
        *(float2*)(og + (size_t)g * D_ + nt * 8 + 2 * t)       = r0;
        *(float2*)(og + (size_t)(g + 8) * D_ + nt * 8 + 2 * t) = r1;
    }
}

// ---------------------------------------------------------------------------
extern "C" void kernel_launch(void* const* d_in, const int* in_sizes, int n_in,
                              void* d_out, int out_size)
{
    const float* x       = (const float*)d_in[0];   // [2,2048,1024]
    const float* cosb    = (const float*)d_in[1];   // [2048,32]
    const float* sinb    = (const float*)d_in[2];   // [2048,32]
    const float* Wqkv    = (const float*)d_in[3];   // [1024,3072]
    const float* bqkv    = (const float*)d_in[4];   // [3072]
    const float* q_scale = (const float*)d_in[5];   // [1024]
    const float* k_scale = (const float*)d_in[6];   // [1024]
    const float* Wout    = (const float*)d_in[7];   // [1024,1024]
    const float* bout    = (const float*)d_in[8];   // [1024]
    float* out = (float*)d_out;                     // [2,2048,1024]

    float* qkv_p = nullptr;
    float* ao_p  = nullptr;
    cudaGetSymbolAddress((void**)&qkv_p, g_qkv);
    cudaGetSymbolAddress((void**)&ao_p, g_ao);
    cudaFuncSetAttribute(attn_tc_kernel, cudaFuncAttributeMaxDynamicSharedMemorySize,
                         ATTN_TC_SMEM);

    // 1) qkv = x @ Wqkv + bqkv   (tf32 tensor cores)
    {
        dim3 grid(QKVW_ / 128, ROWS_ / 128);
        gemm_tf32_bias_kernel<<<grid, 256>>>(x, Wqkv, bqkv, qkv_p, ROWS_, QKVW_, D_);
    }
    // 2) rmsnorm + rope on q,k (in place)
    norm_rope_kernel<<<ROWS_, 256>>>(qkv_p, cosb, sinb, q_scale, k_scale);

    // 3) attention (tf32 tensor cores, flash)
    {
        dim3 grid(N_ / 64, H_, B_);
        attn_tc_kernel<<<grid, 128, ATTN_TC_SMEM>>>(qkv_p, ao_p);
    }
    // 4) out = ao @ Wout + bout   (tf32 tensor cores)
    {
        dim3 grid(D_ / 128, ROWS_ / 128);
        gemm_tf32_bias_kernel<<<grid, 256>>>(ao_p, Wout, bout, out, ROWS_, D_, D_);
    }
}